// round 9
// baseline (speedup 1.0000x reference)
#include <cuda_runtime.h>

#define TB   64      // batch
#define TT   512     // timesteps
#define DIN  64
#define DM   512     // d_model
#define DOUT 64
#define NCB  16      // column blocks
#define NC   32      // cols per CTA
#define NBB  8       // batch blocks
#define NB   8       // batches per CTA
#define GB   128     // persistent grid
#define NT   512     // threads per k_seq CTA (16 warps)

typedef unsigned long long u64;

// ---- device scratch (allocation-free) --------------------------------------
__device__ float g_pre0 [TT * TB * DM];   // [t][b][j]
__device__ float g_h1all[TT * TB * DM];   // [t][b][j]
__device__ float g_h0   [2 * TB * DM];    // ping-pong h0
__device__ float g_h1   [2 * TB * DM];    // ping-pong h1
// per-CTA progress epochs: slot (bb,cb) is monotone per CTA -> no A/B mixing race
__device__ unsigned int g_prog[NBB][NCB];

// packed fp32x2 FMA — kept ONLY in k_pre (measured win there, loss in k_seq)
__device__ __forceinline__ u64 ffma2(u64 a, u64 b, u64 c) {
    u64 d;
    asm("fma.rn.f32x2 %0, %1, %2, %3;" : "=l"(d) : "l"(a), "l"(b), "l"(c));
    return d;
}
__device__ __forceinline__ float f2sum(u64 v) {
    float x, y;
    asm("mov.b64 {%0,%1}, %2;" : "=f"(x), "=f"(y) : "l"(v));
    return x + y;
}

// ---------------------------------------------------------------------------
// k_pre: pre0 = x@Wih0 + bih0 + bhh0 (measured 108us). Also resets progress
// epochs and zeros parity-1 hidden state.
// ---------------------------------------------------------------------------
__global__ void __launch_bounds__(256, 1)
k_pre(const float* __restrict__ data, const float* __restrict__ Wih0,
      const float* __restrict__ bih0, const float* __restrict__ bhh0)
{
    extern __shared__ float sm[];
    float*  xs = sm;                          // [64][64]
    float2* Wp = (float2*)(sm + TB * DIN);    // [32 k2][512 j]
    float*  bs = sm + TB * DIN + 2 * 32 * DM; // [512]

    const int t = blockIdx.x, tid = threadIdx.x;
    if (t == 0 && tid < NBB * NCB) ((unsigned int*)g_prog)[tid] = 0u;
    if (t < 128) {
        int i = t * 256 + tid;
        g_h0[TB * DM + i] = 0.0f;
        g_h1[TB * DM + i] = 0.0f;
    }

    for (int i = tid; i < TB * DIN; i += 256) {
        int b = i >> 6, k = i & 63;
        xs[b * DIN + k] = data[(b * TT + t) * DIN + k];
    }
    for (int i = tid; i < 32 * DM; i += 256) {
        int k2 = i >> 9, j = i & 511;
        Wp[i] = make_float2(Wih0[(2 * k2) * DM + j], Wih0[(2 * k2 + 1) * DM + j]);
    }
    for (int i = tid; i < DM; i += 256) bs[i] = bih0[i] + bhh0[i];
    __syncthreads();

    const int j0 = tid;
    for (int g = 0; g < 8; g++) {
        u64 acc[2][8];
        #pragma unroll
        for (int c = 0; c < 2; c++)
            #pragma unroll
            for (int b = 0; b < 8; b++) acc[c][b] = 0ULL;
        #pragma unroll 8
        for (int k2 = 0; k2 < 32; k2++) {
            u64 w0 = *(const u64*)&Wp[k2 * DM + j0];
            u64 w1 = *(const u64*)&Wp[k2 * DM + j0 + 256];
            #pragma unroll
            for (int b = 0; b < 8; b++) {
                u64 h = *(const u64*)&xs[(g * 8 + b) * DIN + 2 * k2];
                acc[0][b] = ffma2(h, w0, acc[0][b]);
                acc[1][b] = ffma2(h, w1, acc[1][b]);
            }
        }
        #pragma unroll
        for (int b = 0; b < 8; b++) {
            int bg = g * 8 + b;
            g_pre0[(t * TB + bg) * DM + j0]       = f2sum(acc[0][b]) + bs[j0];
            g_pre0[(t * TB + bg) * DM + j0 + 256] = f2sum(acc[1][b]) + bs[j0 + 256];
        }
    }
}

// ---------------------------------------------------------------------------
// arrive: publish this CTA's epoch (release). wait: all 16 peer slots >= tgt
// (slots are per-CTA monotone -> a later epoch implies all earlier arrives).
// The 16 slots share one 64B sector -> one L2 access per poll sweep.
// ---------------------------------------------------------------------------
__device__ __forceinline__ void arrive(int bb, int cb, unsigned int ep)
{
    __threadfence();                  // release all threads' global stores
    __syncthreads();                  // whole CTA fenced before publishing
    if (threadIdx.x == 0)
        *((volatile unsigned int*)&g_prog[bb][cb]) = ep;
}
__device__ __forceinline__ void waitcnt(int bb, unsigned int tgt)
{
    if (threadIdx.x < NCB) {
        volatile unsigned int* p = &g_prog[bb][threadIdx.x];
        while (*p < tgt) { }
        __threadfence();              // acquire
    }
    __syncthreads();
}

// copy 4096 floats (8 batch rows of h) global -> smem, L2-coherent (NT=512)
__device__ __forceinline__ void stage(float* dst, const float* src, int tid)
{
    const float4* s = (const float4*)src;
    float4*       d = (float4*)dst;
    d[tid]      = __ldcg(&s[tid]);
    d[tid + NT] = __ldcg(&s[tid + NT]);
}

// warp-slice GEMM: acc[b] += sum_{kg in [kg0,kg0+8)} h[b][4kg..] . W[kg][lc]
__device__ __forceinline__ void gemm_slice(const float4* __restrict__ Wv,
                                           const float* __restrict__ hbuf,
                                           int kg0, int lc, float acc[8])
{
    #pragma unroll 4
    for (int kg = kg0; kg < kg0 + 8; kg++) {
        float4 wv = Wv[kg * 32 + lc];
        #pragma unroll
        for (int b = 0; b < 8; b++) {
            float4 h = *(const float4*)&hbuf[b * DM + kg * 4]; // broadcast
            acc[b] = fmaf(h.x, wv.x, acc[b]);
            acc[b] = fmaf(h.y, wv.y, acc[b]);
            acc[b] = fmaf(h.z, wv.z, acc[b]);
            acc[b] = fmaf(h.w, wv.w, acc[b]);
        }
    }
}

// ---------------------------------------------------------------------------
// k_seq: 512 steps, 128 persistent CTAs x 512 thr (16 warps, 4/SMSP for
// latency hiding), smem 229504 B. Split-k 16-way; reduction scratch lives in
// the dead 16KB h-buffer of each phase ([128][32] partials = exactly 16KB).
// Pipelined: wait A_t hidden behind h1@Whh1; wait B_t hidden behind phase1_{t+1}.
// Epochs: A_0=1, B_t=2t+2, A_{t+1}=2t+3.
// ---------------------------------------------------------------------------
__global__ void __launch_bounds__(NT, 1)
k_seq(const float* __restrict__ Whh0, const float* __restrict__ Wih1,
      const float* __restrict__ bih1, const float* __restrict__ Whh1,
      const float* __restrict__ bhh1)
{
    extern __shared__ float sm[];
    float4* W0  = (float4*)sm;          // [4096] float4 (Whh0 slice)
    float4* W1  = W0 + 4096;            // Wih1 slice
    float4* W2  = W1 + 4096;            // Whh1 slice
    float*  h0s = sm + 3 * 16384;       // [8][512] = 16KB (also red buffer)
    float*  h1s = h0s + NB * DM;        // [8][512] = 16KB (also red buffer)
    float*  b1s = h1s + NB * DM;        // [32]

    const int tid = threadIdx.x;
    const int cb  = blockIdx.x & (NCB - 1);
    const int bb  = blockIdx.x >> 4;
    const int c0  = cb * NC, b0 = bb * NB;

    for (int idx = tid; idx < 4096; idx += NT) {
        int kg = idx >> 5, c = idx & 31;
        int kb = kg * 4, cg = c0 + c;
        float4 v;
        v.x = Whh0[(kb+0)*DM+cg]; v.y = Whh0[(kb+1)*DM+cg];
        v.z = Whh0[(kb+2)*DM+cg]; v.w = Whh0[(kb+3)*DM+cg];
        W0[idx] = v;
        v.x = Wih1[(kb+0)*DM+cg]; v.y = Wih1[(kb+1)*DM+cg];
        v.z = Wih1[(kb+2)*DM+cg]; v.w = Wih1[(kb+3)*DM+cg];
        W1[idx] = v;
        v.x = Whh1[(kb+0)*DM+cg]; v.y = Whh1[(kb+1)*DM+cg];
        v.z = Whh1[(kb+2)*DM+cg]; v.w = Whh1[(kb+3)*DM+cg];
        W2[idx] = v;
    }
    if (tid < NC) b1s[tid] = bih1[c0 + tid] + bhh1[c0 + tid];

    // prime h1s with zeros (parity-1 buffer, zeroed by k_pre)
    stage(h1s, g_h1 + TB * DM + b0 * DM, tid);
    __syncthreads();

    const int w   = tid >> 5;     // warp = k-slice (0..15); w<8 also batch id
    const int lc  = tid & 31;
    const int kg0 = w * 8;
    float acc[8];

    // ---- prologue: h0_0 = tanh(pre0[0])  (h0_prev = 0 -> no GEMM) ----
    if (w < 8)
        g_h0[(b0 + w) * DM + c0 + lc] =
            tanhf(__ldg(&g_pre0[(b0 + w) * DM + c0 + lc]));
    arrive(bb, cb, 1u);                                   // A_0

    for (int t = 0; t < TT; t++) {
        const int p = t & 1;

        // partial = h1_prev @ Whh1   (hides wait A_t)
        #pragma unroll
        for (int b = 0; b < 8; b++) acc[b] = 0.0f;
        gemm_slice(W2, h1s, kg0, lc, acc);

        waitcnt(bb, (unsigned)(2 * t + 1));               // A_t
        stage(h0s, g_h0 + p * TB * DM + b0 * DM, tid);    // h0_t
        __syncthreads();

        // phase2: partial += h0_t @ Wih1 -> h1_t
        gemm_slice(W1, h0s, kg0, lc, acc);
        __syncthreads();                 // all warps done reading h1s
        #pragma unroll
        for (int b = 0; b < 8; b++) h1s[(w * 8 + b) * 32 + lc] = acc[b];
        __syncthreads();
        if (w < 8) {
            float s = b1s[lc];
            #pragma unroll
            for (int r = 0; r < 16; r++) s += h1s[(r * 8 + w) * 32 + lc];
            float hn = tanhf(s);
            int gi = (b0 + w) * DM + c0 + lc;
            g_h1[p * TB * DM + gi]    = hn;
            g_h1all[t * TB * DM + gi] = hn;
        }
        arrive(bb, cb, (unsigned)(2 * t + 2));            // B_t

        // phase1_{t+1}: h0_t @ Whh0 -> h0_{t+1}   (hides wait B_t)
        if (t + 1 < TT) {
            float pre = (w < 8)
                ? __ldg(&g_pre0[((t + 1) * TB + b0 + w) * DM + c0 + lc]) : 0.0f;
            #pragma unroll
            for (int b = 0; b < 8; b++) acc[b] = 0.0f;
            gemm_slice(W0, h0s, kg0, lc, acc);
            __syncthreads();             // all warps done reading h0s
            #pragma unroll
            for (int b = 0; b < 8; b++) h0s[(w * 8 + b) * 32 + lc] = acc[b];
            __syncthreads();
            if (w < 8) {
                float s = pre;
                #pragma unroll
                for (int r = 0; r < 16; r++) s += h0s[(r * 8 + w) * 32 + lc];
                g_h0[(p ^ 1) * TB * DM + (b0 + w) * DM + c0 + lc] = tanhf(s);
            }
            arrive(bb, cb, (unsigned)(2 * t + 3));        // A_{t+1}
        }

        waitcnt(bb, (unsigned)(2 * t + 2));               // B_t (near-free)
        stage(h1s, g_h1 + p * TB * DM + b0 * DM, tid);    // h1_t
        __syncthreads();
    }
}

// ---------------------------------------------------------------------------
// k_out: out[b][t][:] = h1all[t][b][:] @ Wout + bout
// ---------------------------------------------------------------------------
__global__ void __launch_bounds__(256, 1)
k_out(const float* __restrict__ Wout, const float* __restrict__ bout,
      float* __restrict__ out)
{
    extern __shared__ float sm[];
    float* Ws = sm;                 // [512][64]
    float* hs = Ws + DM * DOUT;     // [64][128] k-chunk

    const int t = blockIdx.x, tid = threadIdx.x;
    for (int i = tid; i < DM * DOUT; i += 256) Ws[i] = Wout[i];

    const int j  = tid & 63;
    const int bq = tid >> 6;
    float acc[16];
    #pragma unroll
    for (int i = 0; i < 16; i++) acc[i] = 0.0f;

    for (int kc = 0; kc < 4; kc++) {
        __syncthreads();
        for (int idx = tid; idx < TB * 128; idx += 256) {
            int b = idx >> 7, kk = idx & 127;
            hs[idx] = g_h1all[(t * TB + b) * DM + kc * 128 + kk];
        }
        __syncthreads();
        for (int kk = 0; kk < 128; kk++) {
            float wv = Ws[(kc * 128 + kk) * DOUT + j];
            #pragma unroll
            for (int i = 0; i < 16; i++)
                acc[i] = fmaf(hs[(bq * 16 + i) * 128 + kk], wv, acc[i]);
        }
    }
    float bj = bout[j];
    #pragma unroll
    for (int i = 0; i < 16; i++) {
        int b = bq * 16 + i;
        out[(b * TT + t) * DOUT + j] = acc[i] + bj;
    }
}

// ---------------------------------------------------------------------------
extern "C" void kernel_launch(void* const* d_in, const int* in_sizes, int n_in,
                              void* d_out, int out_size)
{
    const float* data = (const float*)d_in[0];
    const float* Wih0 = (const float*)d_in[1];
    const float* bih0 = (const float*)d_in[2];
    const float* Whh0 = (const float*)d_in[3];
    const float* bhh0 = (const float*)d_in[4];
    const float* Wih1 = (const float*)d_in[5];
    const float* bih1 = (const float*)d_in[6];
    const float* Whh1 = (const float*)d_in[7];
    const float* bhh1 = (const float*)d_in[8];
    const float* Wout = (const float*)d_in[9];
    const float* bout = (const float*)d_in[10];
    float* out = (float*)d_out;

    cudaFuncSetAttribute(k_pre, cudaFuncAttributeMaxDynamicSharedMemorySize, 149504);
    cudaFuncSetAttribute(k_seq, cudaFuncAttributeMaxDynamicSharedMemorySize, 229504);
    cudaFuncSetAttribute(k_out, cudaFuncAttributeMaxDynamicSharedMemorySize, 163840);

    k_pre<<<TT, 256, 149504>>>(data, Wih0, bih0, bhh0);
    k_seq<<<GB, NT, 229504>>>(Whh0, Wih1, bih1, Whh1, bhh1);
    k_out<<<TT, 256, 163840>>>(Wout, bout, out);
}

// round 11
// speedup vs baseline: 1.6482x; 1.6482x over previous
#include <cuda_runtime.h>

#define TB   64      // batch
#define TT   512     // timesteps
#define DIN  64
#define DM   512     // d_model
#define DOUT 64
#define NCB  16      // column blocks
#define NC   32      // cols per CTA
#define NBB  8       // batch blocks
#define NB   8       // batches per CTA
#define GB   128     // persistent grid
#define NT   256     // threads per k_seq CTA (8 warps — measured optimum)

typedef unsigned long long u64;

// ---- device scratch (allocation-free) --------------------------------------
__device__ float g_pre0 [TT * TB * DM];   // [t][b][j]
__device__ float g_h1all[TT * TB * DM];   // [t][b][j]
__device__ float g_h0   [2 * TB * DM];    // ping-pong h0
__device__ float g_h1   [2 * TB * DM];    // ping-pong h1
// per-CTA progress epochs: slot (bb,cb) is monotone per CTA -> no A/B mixing race
__device__ unsigned int g_prog[NBB][NCB];

// packed fp32x2 FMA — kept ONLY in k_pre (measured win there, loss in k_seq)
__device__ __forceinline__ u64 ffma2(u64 a, u64 b, u64 c) {
    u64 d;
    asm("fma.rn.f32x2 %0, %1, %2, %3;" : "=l"(d) : "l"(a), "l"(b), "l"(c));
    return d;
}
__device__ __forceinline__ float f2sum(u64 v) {
    float x, y;
    asm("mov.b64 {%0,%1}, %2;" : "=f"(x), "=f"(y) : "l"(v));
    return x + y;
}

// ---------------------------------------------------------------------------
// k_pre: pre0 = x@Wih0 + bih0 + bhh0 (measured ~110-160us). Also resets
// progress epochs and zeros parity-1 hidden state.
// ---------------------------------------------------------------------------
__global__ void __launch_bounds__(256, 1)
k_pre(const float* __restrict__ data, const float* __restrict__ Wih0,
      const float* __restrict__ bih0, const float* __restrict__ bhh0)
{
    extern __shared__ float sm[];
    float*  xs = sm;                          // [64][64]
    float2* Wp = (float2*)(sm + TB * DIN);    // [32 k2][512 j]
    float*  bs = sm + TB * DIN + 2 * 32 * DM; // [512]

    const int t = blockIdx.x, tid = threadIdx.x;
    if (t == 0 && tid < NBB * NCB) ((unsigned int*)g_prog)[tid] = 0u;
    if (t < 128) {
        int i = t * 256 + tid;
        g_h0[TB * DM + i] = 0.0f;
        g_h1[TB * DM + i] = 0.0f;
    }

    for (int i = tid; i < TB * DIN; i += 256) {
        int b = i >> 6, k = i & 63;
        xs[b * DIN + k] = data[(b * TT + t) * DIN + k];
    }
    for (int i = tid; i < 32 * DM; i += 256) {
        int k2 = i >> 9, j = i & 511;
        Wp[i] = make_float2(Wih0[(2 * k2) * DM + j], Wih0[(2 * k2 + 1) * DM + j]);
    }
    for (int i = tid; i < DM; i += 256) bs[i] = bih0[i] + bhh0[i];
    __syncthreads();

    const int j0 = tid;
    for (int g = 0; g < 8; g++) {
        u64 acc[2][8];
        #pragma unroll
        for (int c = 0; c < 2; c++)
            #pragma unroll
            for (int b = 0; b < 8; b++) acc[c][b] = 0ULL;
        #pragma unroll 8
        for (int k2 = 0; k2 < 32; k2++) {
            u64 w0 = *(const u64*)&Wp[k2 * DM + j0];
            u64 w1 = *(const u64*)&Wp[k2 * DM + j0 + 256];
            #pragma unroll
            for (int b = 0; b < 8; b++) {
                u64 h = *(const u64*)&xs[(g * 8 + b) * DIN + 2 * k2];
                acc[0][b] = ffma2(h, w0, acc[0][b]);
                acc[1][b] = ffma2(h, w1, acc[1][b]);
            }
        }
        #pragma unroll
        for (int b = 0; b < 8; b++) {
            int bg = g * 8 + b;
            g_pre0[(t * TB + bg) * DM + j0]       = f2sum(acc[0][b]) + bs[j0];
            g_pre0[(t * TB + bg) * DM + j0 + 256] = f2sum(acc[1][b]) + bs[j0 + 256];
        }
    }
}

// ---------------------------------------------------------------------------
// arrive: bar.sync orders all CTA threads' prior global stores before thread
// 0's release-store of the epoch (cumulativity). wait: lanes 0..15 poll the
// 16 per-CTA slots (one 64B sector) with acquire loads; trailing bar.sync
// extends the acquire to the whole CTA. Slots are monotone per CTA, so
// slot >= tgt implies that CTA passed every earlier arrive.
// ---------------------------------------------------------------------------
__device__ __forceinline__ void arrive(int bb, int cb, unsigned int ep)
{
    __syncthreads();
    if (threadIdx.x == 0)
        asm volatile("st.release.gpu.global.u32 [%0], %1;"
                     :: "l"(&g_prog[bb][cb]), "r"(ep) : "memory");
}
__device__ __forceinline__ void waitcnt(int bb, unsigned int tgt)
{
    if (threadIdx.x < NCB) {
        const unsigned int* p = &g_prog[bb][threadIdx.x];
        unsigned int v;
        do {
            asm volatile("ld.acquire.gpu.global.u32 %0, [%1];"
                         : "=r"(v) : "l"(p) : "memory");
        } while (v < tgt);
    }
    __syncthreads();
}

// copy 4096 floats (8 batch rows of h) global -> smem, L2-coherent
__device__ __forceinline__ void stage(float* dst, const float* src, int tid)
{
    const float4* s = (const float4*)src;
    float4*       d = (float4*)dst;
    #pragma unroll
    for (int j = 0; j < 4; j++) d[tid + 256 * j] = __ldcg(&s[tid + 256 * j]);
}

// warp-slice GEMM: acc[b] += sum_{kg in [kg0,kg0+16)} h[b][4kg..] . W[kg][lc]
__device__ __forceinline__ void gemm_slice(const float4* __restrict__ Wv,
                                           const float* __restrict__ hbuf,
                                           int kg0, int lc, float acc[8])
{
    #pragma unroll 4
    for (int kg = kg0; kg < kg0 + 16; kg++) {
        float4 wv = Wv[kg * 32 + lc];
        #pragma unroll
        for (int b = 0; b < 8; b++) {
            float4 h = *(const float4*)&hbuf[b * DM + kg * 4]; // broadcast
            acc[b] = fmaf(h.x, wv.x, acc[b]);
            acc[b] = fmaf(h.y, wv.y, acc[b]);
            acc[b] = fmaf(h.z, wv.z, acc[b]);
            acc[b] = fmaf(h.w, wv.w, acc[b]);
        }
    }
}

// ---------------------------------------------------------------------------
// k_seq: 512 steps, 128 persistent CTAs x 256 thr (8 warps — measured best),
// smem 229504 B. Split-k 8-way; reduction scratch = dead h-buffer of each
// phase. Pipelined: wait A_t hidden behind h1_prev@Whh1; wait B_t hidden
// behind phase1_{t+1}. Epochs: A_0=1, B_t=2t+2, A_{t+1}=2t+3.
// ---------------------------------------------------------------------------
__global__ void __launch_bounds__(NT, 1)
k_seq(const float* __restrict__ Whh0, const float* __restrict__ Wih1,
      const float* __restrict__ bih1, const float* __restrict__ Whh1,
      const float* __restrict__ bhh1)
{
    extern __shared__ float sm[];
    float4* W0  = (float4*)sm;          // [4096] float4 (Whh0 slice)
    float4* W1  = W0 + 4096;            // Wih1 slice
    float4* W2  = W1 + 4096;            // Whh1 slice
    float*  h0s = sm + 3 * 16384;       // [8][512] (also reduction buffer)
    float*  h1s = h0s + NB * DM;        // [8][512] (also reduction buffer)
    float*  b1s = h1s + NB * DM;        // [32]

    const int tid = threadIdx.x;
    const int cb  = blockIdx.x & (NCB - 1);
    const int bb  = blockIdx.x >> 4;
    const int c0  = cb * NC, b0 = bb * NB;

    for (int idx = tid; idx < 4096; idx += NT) {
        int kg = idx >> 5, c = idx & 31;
        int kb = kg * 4, cg = c0 + c;
        float4 v;
        v.x = Whh0[(kb+0)*DM+cg]; v.y = Whh0[(kb+1)*DM+cg];
        v.z = Whh0[(kb+2)*DM+cg]; v.w = Whh0[(kb+3)*DM+cg];
        W0[idx] = v;
        v.x = Wih1[(kb+0)*DM+cg]; v.y = Wih1[(kb+1)*DM+cg];
        v.z = Wih1[(kb+2)*DM+cg]; v.w = Wih1[(kb+3)*DM+cg];
        W1[idx] = v;
        v.x = Whh1[(kb+0)*DM+cg]; v.y = Whh1[(kb+1)*DM+cg];
        v.z = Whh1[(kb+2)*DM+cg]; v.w = Whh1[(kb+3)*DM+cg];
        W2[idx] = v;
    }
    if (tid < NC) b1s[tid] = bih1[c0 + tid] + bhh1[c0 + tid];

    // prime h1s with zeros (parity-1 buffer, zeroed by k_pre)
    stage(h1s, g_h1 + TB * DM + b0 * DM, tid);
    __syncthreads();

    const int w   = tid >> 5;     // warp = k-slice; also batch id in reduction
    const int lc  = tid & 31;
    const int kg0 = w * 16;
    float acc[8];

    // ---- prologue: h0_0 = tanh(pre0[0])  (h0_prev = 0 -> no GEMM) ----
    g_h0[(b0 + w) * DM + c0 + lc] =
        tanhf(__ldg(&g_pre0[(b0 + w) * DM + c0 + lc]));
    arrive(bb, cb, 1u);                                   // A_0

    for (int t = 0; t < TT; t++) {
        const int p = t & 1;

        // partial = h1_prev @ Whh1   (hides wait A_t)
        #pragma unroll
        for (int b = 0; b < 8; b++) acc[b] = 0.0f;
        gemm_slice(W2, h1s, kg0, lc, acc);

        waitcnt(bb, (unsigned)(2 * t + 1));               // A_t
        stage(h0s, g_h0 + p * TB * DM + b0 * DM, tid);    // h0_t
        __syncthreads();

        // phase2: partial += h0_t @ Wih1 -> h1_t
        gemm_slice(W1, h0s, kg0, lc, acc);
        __syncthreads();                 // all warps done reading h1s
        #pragma unroll
        for (int b = 0; b < 8; b++) h1s[(w * 8 + b) * 32 + lc] = acc[b];
        __syncthreads();
        {
            float s = b1s[lc];
            #pragma unroll
            for (int r = 0; r < 8; r++) s += h1s[(r * 8 + w) * 32 + lc];
            float hn = tanhf(s);
            int gi = (b0 + w) * DM + c0 + lc;
            g_h1[p * TB * DM + gi]    = hn;
            g_h1all[t * TB * DM + gi] = hn;
        }
        arrive(bb, cb, (unsigned)(2 * t + 2));            // B_t

        // phase1_{t+1}: h0_t @ Whh0 -> h0_{t+1}   (hides wait B_t)
        if (t + 1 < TT) {
            float pre = __ldg(&g_pre0[((t + 1) * TB + b0 + w) * DM + c0 + lc]);
            #pragma unroll
            for (int b = 0; b < 8; b++) acc[b] = 0.0f;
            gemm_slice(W0, h0s, kg0, lc, acc);
            __syncthreads();             // all warps done reading h0s
            #pragma unroll
            for (int b = 0; b < 8; b++) h0s[(w * 8 + b) * 32 + lc] = acc[b];
            __syncthreads();
            float s = pre;
            #pragma unroll
            for (int r = 0; r < 8; r++) s += h0s[(r * 8 + w) * 32 + lc];
            g_h0[(p ^ 1) * TB * DM + (b0 + w) * DM + c0 + lc] = tanhf(s);
            arrive(bb, cb, (unsigned)(2 * t + 3));        // A_{t+1}
        }

        waitcnt(bb, (unsigned)(2 * t + 2));               // B_t (near-free)
        stage(h1s, g_h1 + p * TB * DM + b0 * DM, tid);    // h1_t
        __syncthreads();
    }
}

// ---------------------------------------------------------------------------
// k_out: out[b][t][:] = h1all[t][b][:] @ Wout + bout
// ---------------------------------------------------------------------------
__global__ void __launch_bounds__(256, 1)
k_out(const float* __restrict__ Wout, const float* __restrict__ bout,
      float* __restrict__ out)
{
    extern __shared__ float sm[];
    float* Ws = sm;                 // [512][64]
    float* hs = Ws + DM * DOUT;     // [64][128] k-chunk

    const int t = blockIdx.x, tid = threadIdx.x;
    for (int i = tid; i < DM * DOUT; i += 256) Ws[i] = Wout[i];

    const int j  = tid & 63;
    const int bq = tid >> 6;
    float acc[16];
    #pragma unroll
    for (int i = 0; i < 16; i++) acc[i] = 0.0f;

    for (int kc = 0; kc < 4; kc++) {
        __syncthreads();
        for (int idx = tid; idx < TB * 128; idx += 256) {
            int b = idx >> 7, kk = idx & 127;
            hs[idx] = g_h1all[(t * TB + b) * DM + kc * 128 + kk];
        }
        __syncthreads();
        for (int kk = 0; kk < 128; kk++) {
            float wv = Ws[(kc * 128 + kk) * DOUT + j];
            #pragma unroll
            for (int i = 0; i < 16; i++)
                acc[i] = fmaf(hs[(bq * 16 + i) * 128 + kk], wv, acc[i]);
        }
    }
    float bj = bout[j];
    #pragma unroll
    for (int i = 0; i < 16; i++) {
        int b = bq * 16 + i;
        out[(b * TT + t) * DOUT + j] = acc[i] + bj;
    }
}

// ---------------------------------------------------------------------------
extern "C" void kernel_launch(void* const* d_in, const int* in_sizes, int n_in,
                              void* d_out, int out_size)
{
    const float* data = (const float*)d_in[0];
    const float* Wih0 = (const float*)d_in[1];
    const float* bih0 = (const float*)d_in[2];
    const float* Whh0 = (const float*)d_in[3];
    const float* bhh0 = (const float*)d_in[4];
    const float* Wih1 = (const float*)d_in[5];
    const float* bih1 = (const float*)d_in[6];
    const float* Whh1 = (const float*)d_in[7];
    const float* bhh1 = (const float*)d_in[8];
    const float* Wout = (const float*)d_in[9];
    const float* bout = (const float*)d_in[10];
    float* out = (float*)d_out;

    cudaFuncSetAttribute(k_pre, cudaFuncAttributeMaxDynamicSharedMemorySize, 149504);
    cudaFuncSetAttribute(k_seq, cudaFuncAttributeMaxDynamicSharedMemorySize, 229504);
    cudaFuncSetAttribute(k_out, cudaFuncAttributeMaxDynamicSharedMemorySize, 163840);

    k_pre<<<TT, 256, 149504>>>(data, Wih0, bih0, bhh0);
    k_seq<<<GB, NT, 229504>>>(Whh0, Wih1, bih1, Whh1, bhh1);
    k_out<<<TT, 256, 163840>>>(Wout, bout, out);
}

// round 14
// speedup vs baseline: 2.5448x; 1.5440x over previous
#include <cuda_runtime.h>

#define TB   64      // batch
#define TT   512     // timesteps
#define DIN  64
#define DM   512     // d_model
#define DOUT 64
#define NCB  16      // column blocks
#define NC   32      // cols per CTA
#define NBB  8       // batch blocks
#define NB   8       // batches per CTA
#define GB   128     // persistent grid
#define NT   256     // threads per k_seq CTA (8 warps — measured optimum)

typedef unsigned long long u64;

// ---- device scratch (allocation-free) --------------------------------------
__device__ float g_pre0 [TT * TB * DM];   // [t][b][j]
__device__ float g_h1all[TT * TB * DM];   // [t][b][j]
__device__ float g_h0   [2 * TB * DM];    // ping-pong h0
__device__ float g_h1   [2 * TB * DM];    // ping-pong h1
// phase-separated monotonic counters: sums can't mix A/B arrivals -> race-free
__device__ unsigned int g_barA[NBB];
__device__ unsigned int g_barB[NBB];

// packed fp32x2 FMA — kept ONLY in k_pre (measured win there, loss in k_seq)
__device__ __forceinline__ u64 ffma2(u64 a, u64 b, u64 c) {
    u64 d;
    asm("fma.rn.f32x2 %0, %1, %2, %3;" : "=l"(d) : "l"(a), "l"(b), "l"(c));
    return d;
}
__device__ __forceinline__ float f2sum(u64 v) {
    float x, y;
    asm("mov.b64 {%0,%1}, %2;" : "=f"(x), "=f"(y) : "l"(v));
    return x + y;
}

// ---------------------------------------------------------------------------
// k_pre: pre0 = x@Wih0 + bih0 + bhh0 (measured ~110us). Also resets barrier
// counters and zeros parity-1 hidden state.
// ---------------------------------------------------------------------------
__global__ void __launch_bounds__(256, 1)
k_pre(const float* __restrict__ data, const float* __restrict__ Wih0,
      const float* __restrict__ bih0, const float* __restrict__ bhh0)
{
    extern __shared__ float sm[];
    float*  xs = sm;                          // [64][64]
    float2* Wp = (float2*)(sm + TB * DIN);    // [32 k2][512 j]
    float*  bs = sm + TB * DIN + 2 * 32 * DM; // [512]

    const int t = blockIdx.x, tid = threadIdx.x;
    if (t == 0 && tid < NBB) { g_barA[tid] = 0u; g_barB[tid] = 0u; }
    if (t < 128) {
        int i = t * 256 + tid;
        g_h0[TB * DM + i] = 0.0f;
        g_h1[TB * DM + i] = 0.0f;
    }

    for (int i = tid; i < TB * DIN; i += 256) {
        int b = i >> 6, k = i & 63;
        xs[b * DIN + k] = data[(b * TT + t) * DIN + k];
    }
    for (int i = tid; i < 32 * DM; i += 256) {
        int k2 = i >> 9, j = i & 511;
        Wp[i] = make_float2(Wih0[(2 * k2) * DM + j], Wih0[(2 * k2 + 1) * DM + j]);
    }
    for (int i = tid; i < DM; i += 256) bs[i] = bih0[i] + bhh0[i];
    __syncthreads();

    const int j0 = tid;
    for (int g = 0; g < 8; g++) {
        u64 acc[2][8];
        #pragma unroll
        for (int c = 0; c < 2; c++)
            #pragma unroll
            for (int b = 0; b < 8; b++) acc[c][b] = 0ULL;
        #pragma unroll 8
        for (int k2 = 0; k2 < 32; k2++) {
            u64 w0 = *(const u64*)&Wp[k2 * DM + j0];
            u64 w1 = *(const u64*)&Wp[k2 * DM + j0 + 256];
            #pragma unroll
            for (int b = 0; b < 8; b++) {
                u64 h = *(const u64*)&xs[(g * 8 + b) * DIN + 2 * k2];
                acc[0][b] = ffma2(h, w0, acc[0][b]);
                acc[1][b] = ffma2(h, w1, acc[1][b]);
            }
        }
        #pragma unroll
        for (int b = 0; b < 8; b++) {
            int bg = g * 8 + b;
            g_pre0[(t * TB + bg) * DM + j0]       = f2sum(acc[0][b]) + bs[j0];
            g_pre0[(t * TB + bg) * DM + j0 + 256] = f2sum(acc[1][b]) + bs[j0 + 256];
        }
    }
}

// ---------------------------------------------------------------------------
// arrive: bar.sync (cross-thread happens-before) + thread0 release-add.
// wait: thread0 polls ONE counter with acquire loads, then bar.sync.
// Counters are phase-separated -> sum >= 16*(t+1) implies every CTA passed
// that phase's arrive for step t (each CTA adds exactly once per step/phase).
// ---------------------------------------------------------------------------
__device__ __forceinline__ void arrive(unsigned int* ctr)
{
    __syncthreads();
    if (threadIdx.x == 0)
        asm volatile("red.release.gpu.global.add.u32 [%0], %1;"
                     :: "l"(ctr), "r"(1u) : "memory");
}
__device__ __forceinline__ void waitcnt(unsigned int* ctr, unsigned int tgt)
{
    if (threadIdx.x == 0) {
        unsigned int v;
        do {
            asm volatile("ld.acquire.gpu.global.u32 %0, [%1];"
                         : "=r"(v) : "l"(ctr) : "memory");
        } while (v < tgt);
    }
    __syncthreads();
}

// copy 4096 floats (8 batch rows of h) global -> smem, L2-coherent
__device__ __forceinline__ void stage(float* dst, const float* src, int tid)
{
    const float4* s = (const float4*)src;
    float4*       d = (float4*)dst;
    #pragma unroll
    for (int j = 0; j < 4; j++) d[tid + 256 * j] = __ldcg(&s[tid + 256 * j]);
}

// single-W warp-slice GEMM (used for Whh1 on h1_prev)
__device__ __forceinline__ void gemm_slice(const float4* __restrict__ Wv,
                                           const float* __restrict__ hbuf,
                                           int kg0, int lc, float acc[8])
{
    #pragma unroll 4
    for (int kg = kg0; kg < kg0 + 16; kg++) {
        float4 wv = Wv[kg * 32 + lc];
        #pragma unroll
        for (int b = 0; b < 8; b++) {
            float4 h = *(const float4*)&hbuf[b * DM + kg * 4]; // broadcast
            acc[b] = fmaf(h.x, wv.x, acc[b]);
            acc[b] = fmaf(h.y, wv.y, acc[b]);
            acc[b] = fmaf(h.z, wv.z, acc[b]);
            acc[b] = fmaf(h.w, wv.w, acc[b]);
        }
    }
}

// fused dual-W pass over ONE h buffer: acc1 += W1.h, acc0 += W0.h
// (halves the broadcast h-LDS traffic vs two separate passes)
__device__ __forceinline__ void gemm_fused(const float4* __restrict__ Wa,
                                           const float4* __restrict__ Wb,
                                           const float* __restrict__ hbuf,
                                           int kg0, int lc,
                                           float acc1[8], float acc0[8])
{
    #pragma unroll 2
    for (int kg = kg0; kg < kg0 + 16; kg++) {
        float4 wa = Wa[kg * 32 + lc];
        float4 wb = Wb[kg * 32 + lc];
        #pragma unroll
        for (int b = 0; b < 8; b++) {
            float4 h = *(const float4*)&hbuf[b * DM + kg * 4]; // broadcast
            acc1[b] = fmaf(h.x, wa.x, acc1[b]);
            acc1[b] = fmaf(h.y, wa.y, acc1[b]);
            acc1[b] = fmaf(h.z, wa.z, acc1[b]);
            acc1[b] = fmaf(h.w, wa.w, acc1[b]);
            acc0[b] = fmaf(h.x, wb.x, acc0[b]);
            acc0[b] = fmaf(h.y, wb.y, acc0[b]);
            acc0[b] = fmaf(h.z, wb.z, acc0[b]);
            acc0[b] = fmaf(h.w, wb.w, acc0[b]);
        }
    }
}

// ---------------------------------------------------------------------------
// k_seq: 512 steps, 128 persistent CTAs x 256 thr, smem 229504 B.
// Per iter t (p = t&1):
//   1. acc2 = h1_{t-1}@Whh1                       [hides wait A_t]
//   2. wait A_t; stage h0s <- h0_t
//   3. fused: acc2 += h0_t@Wih1 ; acc0 = h0_t@Whh0
//   4. reduce acc2 -> h1_t ; arrive B_t
//   5. reduce acc0 -> h0_{t+1} ; arrive A_{t+1}   [peers ~simultaneous]
//   6. wait B_t (skew-only); stage h1s <- h1_t
// ---------------------------------------------------------------------------
__global__ void __launch_bounds__(NT, 1)
k_seq(const float* __restrict__ Whh0, const float* __restrict__ Wih1,
      const float* __restrict__ bih1, const float* __restrict__ Whh1,
      const float* __restrict__ bhh1)
{
    extern __shared__ float sm[];
    float4* W0  = (float4*)sm;          // [4096] float4 (Whh0 slice)
    float4* W1  = W0 + 4096;            // Wih1 slice
    float4* W2  = W1 + 4096;            // Whh1 slice
    float*  h0s = sm + 3 * 16384;       // [8][512] (also acc0 reduction buffer)
    float*  h1s = h0s + NB * DM;        // [8][512] (also acc2 reduction buffer)
    float*  b1s = h1s + NB * DM;        // [32]

    const int tid = threadIdx.x;
    const int cb  = blockIdx.x & (NCB - 1);
    const int bb  = blockIdx.x >> 4;
    const int c0  = cb * NC, b0 = bb * NB;
    unsigned int* barA = &g_barA[bb];
    unsigned int* barB = &g_barB[bb];

    for (int idx = tid; idx < 4096; idx += NT) {
        int kg = idx >> 5, c = idx & 31;
        int kb = kg * 4, cg = c0 + c;
        float4 v;
        v.x = Whh0[(kb+0)*DM+cg]; v.y = Whh0[(kb+1)*DM+cg];
        v.z = Whh0[(kb+2)*DM+cg]; v.w = Whh0[(kb+3)*DM+cg];
        W0[idx] = v;
        v.x = Wih1[(kb+0)*DM+cg]; v.y = Wih1[(kb+1)*DM+cg];
        v.z = Wih1[(kb+2)*DM+cg]; v.w = Wih1[(kb+3)*DM+cg];
        W1[idx] = v;
        v.x = Whh1[(kb+0)*DM+cg]; v.y = Whh1[(kb+1)*DM+cg];
        v.z = Whh1[(kb+2)*DM+cg]; v.w = Whh1[(kb+3)*DM+cg];
        W2[idx] = v;
    }
    if (tid < NC) b1s[tid] = bih1[c0 + tid] + bhh1[c0 + tid];

    // prime h1s with zeros (parity-1 buffer, zeroed by k_pre)
    stage(h1s, g_h1 + TB * DM + b0 * DM, tid);
    __syncthreads();

    const int w   = tid >> 5;     // warp = k-slice; also batch id in reduction
    const int lc  = tid & 31;
    const int kg0 = w * 16;
    float acc2[8], acc0[8];

    // ---- prologue: h0_0 = tanh(pre0[0])  (h0_prev = 0 -> no GEMM) ----
    g_h0[(b0 + w) * DM + c0 + lc] =
        tanhf(__ldg(&g_pre0[(b0 + w) * DM + c0 + lc]));
    arrive(barA);                                         // A_0

    for (int t = 0; t < TT; t++) {
        const int p = t & 1;
        const bool last = (t == TT - 1);

        // 1. acc2 = h1_{t-1} @ Whh1   (hides wait A_t)
        #pragma unroll
        for (int b = 0; b < 8; b++) acc2[b] = 0.0f;
        gemm_slice(W2, h1s, kg0, lc, acc2);

        // 2. wait A_t; stage h0_t
        waitcnt(barA, (unsigned)(t + 1) * NCB);
        stage(h0s, g_h0 + p * TB * DM + b0 * DM, tid);
        __syncthreads();

        // 3. fused pass over h0_t
        float pre = 0.0f;
        if (!last) {
            pre = __ldg(&g_pre0[((t + 1) * TB + b0 + w) * DM + c0 + lc]);
            #pragma unroll
            for (int b = 0; b < 8; b++) acc0[b] = 0.0f;
            gemm_fused(W1, W0, h0s, kg0, lc, acc2, acc0);
        } else {
            gemm_slice(W1, h0s, kg0, lc, acc2);
        }

        // acc2 partials -> h1s (its h-reads ended before the sync in step 2)
        #pragma unroll
        for (int b = 0; b < 8; b++) h1s[(w * 8 + b) * 32 + lc] = acc2[b];
        __syncthreads();                  // S1: h1s partials visible; h0s reads done
        if (!last) {
            #pragma unroll
            for (int b = 0; b < 8; b++) h0s[(w * 8 + b) * 32 + lc] = acc0[b];
        }

        // 4. reduce -> h1_t ; arrive B_t (its bar.sync also publishes h0s partials)
        {
            float s = b1s[lc];
            #pragma unroll
            for (int r = 0; r < 8; r++) s += h1s[(r * 8 + w) * 32 + lc];
            float hn = tanhf(s);
            int gi = (b0 + w) * DM + c0 + lc;
            g_h1[p * TB * DM + gi]    = hn;
            g_h1all[t * TB * DM + gi] = hn;
        }
        arrive(barB);                                     // B_t (S2)

        // 5. reduce -> h0_{t+1} ; arrive A_{t+1}
        if (!last) {
            float s = pre;
            #pragma unroll
            for (int r = 0; r < 8; r++) s += h0s[(r * 8 + w) * 32 + lc];
            g_h0[(p ^ 1) * TB * DM + (b0 + w) * DM + c0 + lc] = tanhf(s);
            arrive(barA);                                 // A_{t+1} (S3)

            // 6. wait B_t (skew-only by now); stage h1_t
            waitcnt(barB, (unsigned)(t + 1) * NCB);       // S4
            stage(h1s, g_h1 + p * TB * DM + b0 * DM, tid);
            __syncthreads();                              // S5
        }
    }
}

// ---------------------------------------------------------------------------
// k_out: out[b][t][:] = h1all[t][b][:] @ Wout + bout
// ---------------------------------------------------------------------------
__global__ void __launch_bounds__(256, 1)
k_out(const float* __restrict__ Wout, const float* __restrict__ bout,
      float* __restrict__ out)
{
    extern __shared__ float sm[];
    float* Ws = sm;                 // [512][64]
    float* hs = Ws + DM * DOUT;     // [64][128] k-chunk

    const int t = blockIdx.x, tid = threadIdx.x;
    for (int i = tid; i < DM * DOUT; i += 256) Ws[i] = Wout[i];

    const int j  = tid & 63;
    const int bq = tid >> 6;
    float acc[16];
    #pragma unroll
    for (int i = 0; i < 16; i++) acc[i] = 0.0f;

    for (int kc = 0; kc < 4; kc++) {
        __syncthreads();
        for (int idx = tid; idx < TB * 128; idx += 256) {
            int b = idx >> 7, kk = idx & 127;
            hs[idx] = g_h1all[(t * TB + b) * DM + kc * 128 + kk];
        }
        __syncthreads();
        for (int kk = 0; kk < 128; kk++) {
            float wv = Ws[(kc * 128 + kk) * DOUT + j];
            #pragma unroll
            for (int i = 0; i < 16; i++)
                acc[i] = fmaf(hs[(bq * 16 + i) * 128 + kk], wv, acc[i]);
        }
    }
    float bj = bout[j];
    #pragma unroll
    for (int i = 0; i < 16; i++) {
        int b = bq * 16 + i;
        out[(b * TT + t) * DOUT + j] = acc[i] + bj;
    }
}

// ---------------------------------------------------------------------------
extern "C" void kernel_launch(void* const* d_in, const int* in_sizes, int n_in,
                              void* d_out, int out_size)
{
    const float* data = (const float*)d_in[0];
    const float* Wih0 = (const float*)d_in[1];
    const float* bih0 = (const float*)d_in[2];
    const float* Whh0 = (const float*)d_in[3];
    const float* bhh0 = (const float*)d_in[4];
    const float* Wih1 = (const float*)d_in[5];
    const float* bih1 = (const float*)d_in[6];
    const float* Whh1 = (const float*)d_in[7];
    const float* bhh1 = (const float*)d_in[8];
    const float* Wout = (const float*)d_in[9];
    const float* bout = (const float*)d_in[10];
    float* out = (float*)d_out;

    cudaFuncSetAttribute(k_pre, cudaFuncAttributeMaxDynamicSharedMemorySize, 149504);
    cudaFuncSetAttribute(k_seq, cudaFuncAttributeMaxDynamicSharedMemorySize, 229504);
    cudaFuncSetAttribute(k_out, cudaFuncAttributeMaxDynamicSharedMemorySize, 163840);

    k_pre<<<TT, 256, 149504>>>(data, Wih0, bih0, bhh0);
    k_seq<<<GB, NT, 229504>>>(Whh0, Wih1, bih1, Whh1, bhh1);
    k_out<<<TT, 256, 163840>>>(Wout, bout, out);
}